// round 2
// baseline (speedup 1.0000x reference)
#include <cuda_runtime.h>

// EFLSTM: multimodal concat -> LSTM(T=256) -> MLP head.
// Round 1: correct fp32 SIMT implementation.
//   - one fused kernel per timestep (GEMM over K=1433 = [h | x_t] + gate nonlinearity + cell update)
//   - h double-buffered in __device__ globals to avoid cross-block RAW races
//   - 258 kernel launches total, all graph-capturable, no allocations.

#define BB     256
#define TT     256
#define D_TXT  300
#define D_AUD  74
#define D_VIS  35
#define DD     409
#define HH     1024
#define G4     4096
#define NCELL  512
#define KPAD   1440   // ceil((HH + DD)/16)*16 = 90 tiles of 16

__device__ float g_h[2][BB * HH];
__device__ float g_c[BB * HH];

__global__ void init_kernel() {
    int i = blockIdx.x * blockDim.x + threadIdx.x;
    if (i < BB * HH) {
        g_h[0][i] = 0.f;
        g_c[i]    = 0.f;
    }
}

// One LSTM timestep.
// Grid: (64, 4). Block (bx, by) owns rows m0 = by*64 .. +63 (batch) and
// h-columns j0 = bx*16 .. +15. It computes the 64 gate columns
// {band*1024 + j0 + jj : band in 0..3, jj in 0..15} for its 64 rows,
// i.e. a 64x64 GEMM tile over K = 1433 ([h_prev | x_t]), then applies the
// LSTM cell update for its (row, j) patch.
__global__ __launch_bounds__(256) void step_kernel(
    const float* __restrict__ xt, const float* __restrict__ xa, const float* __restrict__ xv,
    const float* __restrict__ Whh, const float* __restrict__ Wih,
    const float* __restrict__ bih, const float* __restrict__ bhh, int t)
{
    __shared__ float As[64][17];        // A tile: rows x k (padded)
    __shared__ float Bs[64][17];        // B tile: gate-cols x k (padded)
    __shared__ float gs[4][64][16];     // gates staging: band x row x jj

    const int rb = t & 1;               // read buffer
    const int wb = rb ^ 1;              // write buffer
    const int m0 = blockIdx.y * 64;
    const int j0 = blockIdx.x * 16;
    const int tid = threadIdx.x;
    const int tx  = tid & 15;
    const int ty  = tid >> 4;
    const int lr  = tid >> 2;           // load row within tile (0..63)
    const int lq  = tid & 3;            // load quarter (0..3) -> 4 consecutive k

    // gate column this thread loads B for
    const int gcB = ((lr >> 4) * HH) + j0 + (lr & 15);
    const float* __restrict__ hread = g_h[rb];

    float acc[4][4];
    #pragma unroll
    for (int i = 0; i < 4; i++)
        #pragma unroll
        for (int j = 0; j < 4; j++) acc[i][j] = 0.f;

    for (int k0 = 0; k0 < KPAD; k0 += 16) {
        if (k0 + 16 <= HH) {
            // recurrent region: vectorized loads (all aligned)
            const float4 va = *(const float4*)&hread[(m0 + lr) * HH + k0 + lq * 4];
            As[lr][lq*4+0] = va.x; As[lr][lq*4+1] = va.y;
            As[lr][lq*4+2] = va.z; As[lr][lq*4+3] = va.w;
            const float4 vb = *(const float4*)&Whh[(size_t)gcB * HH + k0 + lq * 4];
            Bs[lr][lq*4+0] = vb.x; Bs[lr][lq*4+1] = vb.y;
            Bs[lr][lq*4+2] = vb.z; Bs[lr][lq*4+3] = vb.w;
        } else {
            // input region: k - HH indexes the concatenated modalities
            const int m = m0 + lr;
            const int base = m * TT + t;
            #pragma unroll
            for (int u = 0; u < 4; u++) {
                const int k = k0 + lq * 4 + u;
                const int d = k - HH;
                float va = 0.f, vb = 0.f;
                if (d < DD) {
                    if (d < D_TXT)               va = xt[(size_t)base * D_TXT + d];
                    else if (d < D_TXT + D_AUD)  va = xa[(size_t)base * D_AUD + (d - D_TXT)];
                    else                         va = xv[(size_t)base * D_VIS + (d - D_TXT - D_AUD)];
                    vb = Wih[(size_t)gcB * DD + d];
                }
                As[lr][lq*4+u] = va;
                Bs[lr][lq*4+u] = vb;
            }
        }
        __syncthreads();

        #pragma unroll
        for (int kk = 0; kk < 16; kk++) {
            float a[4], b[4];
            #pragma unroll
            for (int i = 0; i < 4; i++) a[i] = As[ty*4 + i][kk];
            #pragma unroll
            for (int j = 0; j < 4; j++) b[j] = Bs[tx*4 + j][kk];
            #pragma unroll
            for (int i = 0; i < 4; i++)
                #pragma unroll
                for (int j = 0; j < 4; j++)
                    acc[i][j] += a[i] * b[j];
        }
        __syncthreads();
    }

    // bias + stage gates into smem grouped by band
    #pragma unroll
    for (int i = 0; i < 4; i++) {
        const int row = ty*4 + i;
        #pragma unroll
        for (int j = 0; j < 4; j++) {
            const int n    = tx*4 + j;
            const int band = n >> 4;
            const int jj   = n & 15;
            const int gc   = band * HH + j0 + jj;
            gs[band][row][jj] = acc[i][j] + bih[gc] + bhh[gc];
        }
    }
    __syncthreads();

    // cell update: i,f,g,o -> c,h (PyTorch LSTMCell gate order)
    float* __restrict__ hwrite = g_h[wb];
    for (int e = tid; e < 64 * 16; e += 256) {
        const int row = e >> 4;
        const int jj  = e & 15;
        const float gi = gs[0][row][jj];
        const float gf = gs[1][row][jj];
        const float gg = gs[2][row][jj];
        const float go = gs[3][row][jj];
        const float si = 1.f / (1.f + __expf(-gi));
        const float sf = 1.f / (1.f + __expf(-gf));
        const float tg = tanhf(gg);
        const float so = 1.f / (1.f + __expf(-go));
        const int idx = (m0 + row) * HH + j0 + jj;
        const float c = sf * g_c[idx] + si * tg;
        g_c[idx]    = c;
        hwrite[idx] = so * tanhf(c);
    }
}

// MLP head: out[b] = W2 @ relu(W1 @ h_last[b] + b1) + b2. One block per batch row.
__global__ __launch_bounds__(256) void mlp_kernel(
    const float* __restrict__ W1, const float* __restrict__ b1,
    const float* __restrict__ W2, const float* __restrict__ b2,
    float* __restrict__ out)
{
    __shared__ float hrow[HH];
    __shared__ float red[256];
    const int b   = blockIdx.x;
    const int tid = threadIdx.x;

    const float* __restrict__ h = &g_h[0][b * HH];   // T=256 even -> final h in buf 0
    for (int k = tid; k < HH; k += 256) hrow[k] = h[k];
    __syncthreads();

    float sum = 0.f;
    for (int cc = tid; cc < NCELL; cc += 256) {
        const float* __restrict__ w = &W1[(size_t)cc * HH];
        float acc = b1[cc];
        for (int k = 0; k < HH; k += 4) {
            const float4 wv = *(const float4*)&w[k];
            acc += hrow[k] * wv.x + hrow[k+1] * wv.y + hrow[k+2] * wv.z + hrow[k+3] * wv.w;
        }
        const float hid = fmaxf(acc, 0.f);
        sum += hid * W2[cc];
    }
    red[tid] = sum;
    __syncthreads();
    for (int s = 128; s > 0; s >>= 1) {
        if (tid < s) red[tid] += red[tid + s];
        __syncthreads();
    }
    if (tid == 0) out[b] = red[0] + b2[0];
}

extern "C" void kernel_launch(void* const* d_in, const int* in_sizes, int n_in,
                              void* d_out, int out_size)
{
    const float* xt  = (const float*)d_in[0];
    const float* xa  = (const float*)d_in[1];
    const float* xv  = (const float*)d_in[2];
    const float* Wih = (const float*)d_in[3];
    const float* Whh = (const float*)d_in[4];
    const float* bih = (const float*)d_in[5];
    const float* bhh = (const float*)d_in[6];
    const float* W1  = (const float*)d_in[7];
    const float* b1  = (const float*)d_in[8];
    const float* W2  = (const float*)d_in[9];
    const float* b2  = (const float*)d_in[10];
    float* out = (float*)d_out;

    init_kernel<<<(BB * HH + 255) / 256, 256>>>();
    for (int t = 0; t < TT; t++)
        step_kernel<<<dim3(64, 4), 256>>>(xt, xa, xv, Whh, Wih, bih, bhh, t);
    mlp_kernel<<<BB, 256>>>(W1, b1, W2, b2, out);
}

// round 5
// speedup vs baseline: 1.7157x; 1.7157x over previous
#include <cuda_runtime.h>
#include <cuda_bf16.h>
#include <cstdint>

// EFLSTM via warp-level bf16x3 mma.sync.
//   phase 1: xg[t,b,:] = x @ Wih^T + bias   (parallel GEMM, fp32, 1GB scratch)
//   phase 2: 256 sequential steps: gates = h @ Whh^T + xg; fused LSTM cell update
//   phase 3: MLP head
// Gate cols permuted n = j*4 + band so cell update is CTA-local.
// bf16x3: Ah*Bh + Al*Bh + Ah*Bl accumulated fp32.

#define BB 256
#define TT 256
#define D_TXT 300
#define D_AUD 74
#define D_VIS 35
#define DD 409
#define HH 1024
#define G4 4096
#define XP 448
#define NCELL 512

// ---------------- device scratch ----------------
__device__ __nv_bfloat16 g_h[2][2][BB * HH];              // [buf][hi/lo]
__device__ float g_c[BB * HH];
__device__ float g_hf[BB * HH];
__device__ __nv_bfloat16 g_wpk[2][(size_t)G4 * HH];       // packed Whh hi/lo  [n=j*4+band][k]
__device__ __nv_bfloat16 g_wipk[2][(size_t)G4 * XP];      // packed Wih hi/lo
__device__ __nv_bfloat16 g_xpk[2][(size_t)TT * BB * XP];  // packed x hi/lo, row = t*BB+b
__device__ float g_bsum[G4];                              // permuted bias
__device__ float g_xg[(size_t)TT * BB * G4];              // xg + bias, fp32

// ---------------- helpers ----------------
__device__ __forceinline__ uint32_t s2u(const void* p) {
    uint32_t a;
    asm("{ .reg .u64 t; cvta.to.shared.u64 t, %1; cvt.u32.u64 %0, t; }" : "=r"(a) : "l"(p));
    return a;
}
#define CP16(d, s) asm volatile("cp.async.cg.shared.global [%0], [%1], 16;" ::"r"(d), "l"(s) : "memory")
#define CPCOMMIT() asm volatile("cp.async.commit_group;" ::: "memory")

// one K=64 chunk. Warp tile = (TM*16) x 32. A rows at mbase, B rows at nbase.
// A,B smem: row-major [rows][64 bf16], 128B/row, 16B-unit swizzle: off ^ ((row&7)<<4).
template <int TM>
__device__ __forceinline__ void gemm_chunk(uint32_t abuf, uint32_t bbuf, int mbase, int nbase,
                                           int lane, float acc[TM][4][4]) {
#pragma unroll
    for (int kk = 0; kk < 4; kk++) {
        uint32_t a[TM][4];
#pragma unroll
        for (int tm = 0; tm < TM; tm++) {
            // lanes 0-15: rows +0..15 at k-half 0; lanes 16-31: same rows at k-half 1
            const uint32_t row = (uint32_t)(mbase + tm * 16 + (lane & 15));
            const uint32_t kb = (uint32_t)(kk * 32) + ((uint32_t)(lane >> 4) << 4);
            const uint32_t addr = abuf + row * 128u + (kb ^ ((row & 7u) << 4));
            asm volatile("ldmatrix.sync.aligned.m8n8.x4.shared.b16 {%0,%1,%2,%3}, [%4];"
                         : "=r"(a[tm][0]), "=r"(a[tm][1]), "=r"(a[tm][2]), "=r"(a[tm][3])
                         : "r"(addr));
        }
        uint32_t b[2][4];
#pragma unroll
        for (int tn = 0; tn < 2; tn++) {
            // NON-trans x4 for B stored [n][k]:
            //  matrix0: n rows 0-7, k-half 0  -> b0 of first n8
            //  matrix1: n rows 0-7, k-half 1  -> b1 of first n8
            //  matrix2: n rows 8-15, k-half 0 -> b0 of second n8
            //  matrix3: n rows 8-15, k-half 1 -> b1 of second n8
            const uint32_t g = (uint32_t)(lane >> 3);
            const uint32_t row = (uint32_t)(nbase + tn * 16) + ((g >> 1) << 3) + (uint32_t)(lane & 7);
            const uint32_t kb = (uint32_t)(kk * 32) + ((g & 1u) << 4);
            const uint32_t addr = bbuf + row * 128u + (kb ^ ((row & 7u) << 4));
            asm volatile("ldmatrix.sync.aligned.m8n8.x4.shared.b16 {%0,%1,%2,%3}, [%4];"
                         : "=r"(b[tn][0]), "=r"(b[tn][1]), "=r"(b[tn][2]), "=r"(b[tn][3])
                         : "r"(addr));
        }
#pragma unroll
        for (int tm = 0; tm < TM; tm++)
#pragma unroll
            for (int tn = 0; tn < 4; tn++) {
                asm volatile(
                    "mma.sync.aligned.m16n8k16.row.col.f32.bf16.bf16.f32 "
                    "{%0,%1,%2,%3}, {%4,%5,%6,%7}, {%8,%9}, {%0,%1,%2,%3};"
                    : "+f"(acc[tm][tn][0]), "+f"(acc[tm][tn][1]),
                      "+f"(acc[tm][tn][2]), "+f"(acc[tm][tn][3])
                    : "r"(a[tm][0]), "r"(a[tm][1]), "r"(a[tm][2]), "r"(a[tm][3]),
                      "r"(b[tn >> 1][(tn & 1) * 2]), "r"(b[tn >> 1][(tn & 1) * 2 + 1]));
            }
    }
}

template <int TM>
__device__ __forceinline__ void store_acc(float* sacc, int pitch, float acc[TM][4][4],
                                          int mbase, int nbase, int lane) {
#pragma unroll
    for (int tm = 0; tm < TM; tm++)
#pragma unroll
        for (int tn = 0; tn < 4; tn++) {
            const int r = mbase + tm * 16 + (lane >> 2);
            const int cc = nbase + tn * 8 + (lane & 3) * 2;
            *(float2*)&sacc[r * pitch + cc] = make_float2(acc[tm][tn][0], acc[tm][tn][1]);
            *(float2*)&sacc[(r + 8) * pitch + cc] = make_float2(acc[tm][tn][2], acc[tm][tn][3]);
        }
}

// ---------------- prep kernels ----------------
__global__ void init_kernel() {
    int i = blockIdx.x * blockDim.x + threadIdx.x;
    if (i < BB * HH) {
        g_h[0][0][i] = __float2bfloat16(0.f);
        g_h[0][1][i] = __float2bfloat16(0.f);
        g_c[i] = 0.f;
    }
}

__global__ void prep_w(const float* __restrict__ Whh) {
    size_t i = (size_t)blockIdx.x * 256 + threadIdx.x;
    if (i >= (size_t)G4 * HH) return;
    int n = (int)(i / HH), k = (int)(i % HH);
    int j = n >> 2, band = n & 3, gc = band * HH + j;
    float w = Whh[(size_t)gc * HH + k];
    __nv_bfloat16 hi = __float2bfloat16(w);
    g_wpk[0][i] = hi;
    g_wpk[1][i] = __float2bfloat16(w - __bfloat162float(hi));
}

__global__ void prep_wi(const float* __restrict__ Wih, const float* __restrict__ bih,
                        const float* __restrict__ bhh) {
    size_t i = (size_t)blockIdx.x * 256 + threadIdx.x;
    if (i >= (size_t)G4 * XP) return;
    int n = (int)(i / XP), k = (int)(i % XP);
    int j = n >> 2, band = n & 3, gc = band * HH + j;
    float w = (k < DD) ? Wih[(size_t)gc * DD + k] : 0.f;
    __nv_bfloat16 hi = __float2bfloat16(w);
    g_wipk[0][i] = hi;
    g_wipk[1][i] = __float2bfloat16(w - __bfloat162float(hi));
    if (k == 0) g_bsum[n] = bih[gc] + bhh[gc];
}

__global__ void prep_x(const float* __restrict__ xt, const float* __restrict__ xa,
                       const float* __restrict__ xv) {
    size_t i = (size_t)blockIdx.x * 256 + threadIdx.x;
    if (i >= (size_t)TT * BB * XP) return;
    int d = (int)(i % XP);
    size_t tb = i / XP;
    int b = (int)(tb % BB), t = (int)(tb / BB);
    float v = 0.f;
    if (d < D_TXT)              v = xt[((size_t)b * TT + t) * D_TXT + d];
    else if (d < D_TXT + D_AUD) v = xa[((size_t)b * TT + t) * D_AUD + (d - D_TXT)];
    else if (d < DD)            v = xv[((size_t)b * TT + t) * D_VIS + (d - D_TXT - D_AUD)];
    __nv_bfloat16 hi = __float2bfloat16(v);
    g_xpk[0][i] = hi;
    g_xpk[1][i] = __float2bfloat16(v - __bfloat162float(hi));
}

// ---------------- xg GEMM: xg = x @ Wih^T + bias ----------------
// 128x128 tiles, grid (32, 512). rows = t*BB+b. 21 iters (3 terms x 7 chunks of 64).
#define XG_PITCH 132
__global__ __launch_bounds__(256, 1) void xg_kernel() {
    extern __shared__ char dsm[];
    const int tid = threadIdx.x;
    const int lane = tid & 31, wid = tid >> 5;
    const int wy = wid >> 2, wx = wid & 3;
    const int r0 = blockIdx.y * 128, n0 = blockIdx.x * 128;
    const uint32_t sb = s2u(dsm);
    const uint32_t Ab[2] = {sb, sb + 16384u}, Bb[2] = {sb + 32768u, sb + 49152u};
    const int lrow = tid & 127;
    const bool isA = tid < 128;
    const uint32_t swz = ((uint32_t)(lrow & 7)) << 4;

    float acc[4][4][4];
#pragma unroll
    for (int i = 0; i < 4; i++)
#pragma unroll
        for (int j = 0; j < 4; j++)
#pragma unroll
            for (int k = 0; k < 4; k++) acc[i][j][k] = 0.f;

    {
        const char* src = isA ? (const char*)(g_xpk[0] + (size_t)(r0 + lrow) * XP)
                              : (const char*)(g_wipk[0] + (size_t)(n0 + lrow) * XP);
        const uint32_t d = (isA ? Ab[0] : Bb[0]) + (uint32_t)lrow * 128u;
#pragma unroll
        for (int s = 0; s < 8; s++) CP16(d + ((uint32_t)(s * 16) ^ swz), src + s * 16);
        CPCOMMIT();
    }
    for (int it = 0; it < 21; it++) {
        if (it + 1 < 21) {
            const int nx = it + 1;
            const int term = (nx >= 14) ? 2 : (nx >= 7 ? 1 : 0);
            const int ck = nx - term * 7;
            const char* src = isA
                ? (const char*)(g_xpk[term == 1 ? 1 : 0] + (size_t)(r0 + lrow) * XP + ck * 64)
                : (const char*)(g_wipk[term == 2 ? 1 : 0] + (size_t)(n0 + lrow) * XP + ck * 64);
            const uint32_t d = (isA ? Ab[nx & 1] : Bb[nx & 1]) + (uint32_t)lrow * 128u;
#pragma unroll
            for (int s = 0; s < 8; s++) CP16(d + ((uint32_t)(s * 16) ^ swz), src + s * 16);
            CPCOMMIT();
            asm volatile("cp.async.wait_group 1;" ::: "memory");
        } else {
            asm volatile("cp.async.wait_group 0;" ::: "memory");
        }
        __syncthreads();
        gemm_chunk<4>(Ab[it & 1], Bb[it & 1], wy * 64, wx * 32, lane, acc);
        __syncthreads();
    }

    float* sacc = (float*)dsm;
    store_acc<4>(sacc, XG_PITCH, acc, wy * 64, wx * 32, lane);
    __syncthreads();
    for (int e = tid; e < 128 * 32; e += 256) {
        const int m = e >> 5, q = e & 31;
        float4 g = *(float4*)&sacc[m * XG_PITCH + q * 4];
        const float4 bs = *(const float4*)&g_bsum[n0 + q * 4];
        g.x += bs.x; g.y += bs.y; g.z += bs.z; g.w += bs.w;
        *(float4*)&g_xg[(size_t)(r0 + m) * G4 + n0 + q * 4] = g;
    }
}

// ---------------- LSTM step: gates = h @ Whh^T + xg; cell update ----------------
// 128(m) x 64(n) tiles, grid (64, 2) = 128 CTAs. 48 iters (3 terms x 16 chunks).
#define ST_PITCH 68
__global__ __launch_bounds__(256, 1) void step_kernel(int t) {
    extern __shared__ char dsm[];
    const int tid = threadIdx.x;
    const int lane = tid & 31, wid = tid >> 5;
    const int wy = wid >> 1, wx = wid & 1;     // warp grid 4(m) x 2(n), warp tile 32x32
    const int m0 = blockIdx.y * 128, n0 = blockIdx.x * 64;
    const int rb = t & 1, wb = rb ^ 1;
    const uint32_t sb = s2u(dsm);
    const uint32_t Ab[2] = {sb, sb + 16384u};
    const uint32_t Bb[2] = {sb + 32768u, sb + 40960u};

    float acc[2][4][4];
#pragma unroll
    for (int i = 0; i < 2; i++)
#pragma unroll
        for (int j = 0; j < 4; j++)
#pragma unroll
            for (int k = 0; k < 4; k++) acc[i][j][k] = 0.f;

    // loader: threads 0-127 -> A row tid (8x16B); threads 128-255 -> B row/half (4x16B)
    const int arow = tid;
    const int bidx = tid - 128;
    const int brow = bidx >> 1, bhalf = bidx & 1;

#pragma unroll 1
    for (int nx = 0; nx < 49; nx++) {
        if (nx < 48) {
            const int term = nx >> 4, ck = nx & 15;
            const int buf = nx & 1;
            if (tid < 128) {
                const char* src = (const char*)(g_h[rb][term == 1 ? 1 : 0]
                                                + (size_t)(m0 + arow) * HH + ck * 64);
                const uint32_t d = Ab[buf] + (uint32_t)arow * 128u;
                const uint32_t swz = ((uint32_t)(arow & 7)) << 4;
#pragma unroll
                for (int s = 0; s < 8; s++) CP16(d + ((uint32_t)(s * 16) ^ swz), src + s * 16);
            } else {
                const char* src = (const char*)(g_wpk[term == 2 ? 1 : 0]
                                                + (size_t)(n0 + brow) * HH + ck * 64)
                                  + bhalf * 64;
                const uint32_t d = Bb[buf] + (uint32_t)brow * 128u;
                const uint32_t swz = ((uint32_t)(brow & 7)) << 4;
#pragma unroll
                for (int s = 0; s < 4; s++)
                    CP16(d + ((uint32_t)(bhalf * 64 + s * 16) ^ swz), src + s * 16);
            }
            CPCOMMIT();
        }
        if (nx >= 1) {
            if (nx < 48) asm volatile("cp.async.wait_group 1;" ::: "memory");
            else         asm volatile("cp.async.wait_group 0;" ::: "memory");
            __syncthreads();
            gemm_chunk<2>(Ab[(nx - 1) & 1], Bb[(nx - 1) & 1], wy * 32, wx * 32, lane, acc);
            __syncthreads();
        }
    }

    float* sacc = (float*)dsm;
    store_acc<2>(sacc, ST_PITCH, acc, wy * 32, wx * 32, lane);
    __syncthreads();

    // cell update: packed n -> j = n>>2, bands i,f,g,o = n&3
    for (int e = tid; e < 128 * 16; e += 256) {
        const int m = e >> 4, q = e & 15;
        const float4 g = *(float4*)&sacc[m * ST_PITCH + q * 4];
        const size_t grow = (size_t)t * BB + (m0 + m);
        const float4 xgv = *(const float4*)&g_xg[grow * G4 + n0 + q * 4];
        const float gi = g.x + xgv.x;
        const float gf = g.y + xgv.y;
        const float gg = g.z + xgv.z;
        const float go = g.w + xgv.w;
        const float si = 1.f / (1.f + __expf(-gi));
        const float sf = 1.f / (1.f + __expf(-gf));
        const float tg = tanhf(gg);
        const float so = 1.f / (1.f + __expf(-go));
        const int j = (n0 >> 2) + q;
        const size_t idx = (size_t)(m0 + m) * HH + j;
        const float c = sf * g_c[idx] + si * tg;
        g_c[idx] = c;
        const float h = so * tanhf(c);
        const __nv_bfloat16 hh = __float2bfloat16(h);
        g_h[wb][0][idx] = hh;
        g_h[wb][1][idx] = __float2bfloat16(h - __bfloat162float(hh));
        if (t == TT - 1) g_hf[idx] = h;
    }
}

// ---------------- MLP head ----------------
__global__ __launch_bounds__(256) void mlp_kernel(
    const float* __restrict__ W1, const float* __restrict__ b1,
    const float* __restrict__ W2, const float* __restrict__ b2,
    float* __restrict__ out) {
    __shared__ float hrow[HH];
    __shared__ float red[256];
    const int b = blockIdx.x;
    const int tid = threadIdx.x;

    const float* __restrict__ h = &g_hf[(size_t)b * HH];
    for (int k = tid; k < HH; k += 256) hrow[k] = h[k];
    __syncthreads();

    float sum = 0.f;
    for (int cc = tid; cc < NCELL; cc += 256) {
        const float* __restrict__ w = &W1[(size_t)cc * HH];
        float acc = b1[cc];
        for (int k = 0; k < HH; k += 4) {
            const float4 wv = *(const float4*)&w[k];
            acc += hrow[k] * wv.x + hrow[k + 1] * wv.y + hrow[k + 2] * wv.z + hrow[k + 3] * wv.w;
        }
        sum += fmaxf(acc, 0.f) * W2[cc];
    }
    red[tid] = sum;
    __syncthreads();
    for (int s = 128; s > 0; s >>= 1) {
        if (tid < s) red[tid] += red[tid + s];
        __syncthreads();
    }
    if (tid == 0) out[b] = red[0] + b2[0];
}

// ---------------- launch ----------------
extern "C" void kernel_launch(void* const* d_in, const int* in_sizes, int n_in,
                              void* d_out, int out_size) {
    const float* xt  = (const float*)d_in[0];
    const float* xa  = (const float*)d_in[1];
    const float* xv  = (const float*)d_in[2];
    const float* Wih = (const float*)d_in[3];
    const float* Whh = (const float*)d_in[4];
    const float* bih = (const float*)d_in[5];
    const float* bhh = (const float*)d_in[6];
    const float* W1  = (const float*)d_in[7];
    const float* b1  = (const float*)d_in[8];
    const float* W2  = (const float*)d_in[9];
    const float* b2  = (const float*)d_in[10];
    float* out = (float*)d_out;

    const int DSM_XG = 69632;   // max(64KB bufs, 128*132*4 staging)
    const int DSM_ST = 49152;   // 2*(16KB A) + 2*(8KB B); staging 128*68*4 = 34816 fits
    cudaFuncSetAttribute(xg_kernel, cudaFuncAttributeMaxDynamicSharedMemorySize, DSM_XG);
    cudaFuncSetAttribute(step_kernel, cudaFuncAttributeMaxDynamicSharedMemorySize, DSM_ST);

    init_kernel<<<(BB * HH + 255) / 256, 256>>>();
    prep_w<<<(int)(((size_t)G4 * HH + 255) / 256), 256>>>(Whh);
    prep_wi<<<(int)(((size_t)G4 * XP + 255) / 256), 256>>>(Wih, bih, bhh);
    prep_x<<<(int)(((size_t)TT * BB * XP + 255) / 256), 256>>>(xt, xa, xv);
    xg_kernel<<<dim3(32, 512), 256, DSM_XG>>>();
    for (int t = 0; t < TT; t++)
        step_kernel<<<dim3(64, 2), 256, DSM_ST>>>(t);
    mlp_kernel<<<BB, 256>>>(W1, b1, W2, b2, out);
}

// round 6
// speedup vs baseline: 2.3372x; 1.3622x over previous
#include <cuda_runtime.h>
#include <cuda_bf16.h>
#include <cstdint>

// EFLSTM via warp-level bf16x3 mma.sync, fused-3-term chunks + 3-stage pipeline.
//   phase 1: xg[t,b,:] = x @ Wih^T + bias   (parallel GEMM, fp32, 1GB scratch)
//   phase 2: 256 sequential steps: gates = h @ Whh^T + xg; fused LSTM cell update
//   phase 3: MLP head
// Gate cols permuted n = j*4 + band so cell update is CTA-local.
// bf16x3: Ah*Bh + Al*Bh + Ah*Bl accumulated fp32, all 3 terms per K-chunk.

#define BB 256
#define TT 256
#define D_TXT 300
#define D_AUD 74
#define D_VIS 35
#define DD 409
#define HH 1024
#define G4 4096
#define XP 448
#define NCELL 512

// ---------------- device scratch ----------------
__device__ __nv_bfloat16 g_h[2][2][BB * HH];              // [buf][hi/lo]
__device__ float g_c[BB * HH];
__device__ float g_hf[BB * HH];
__device__ __nv_bfloat16 g_wpk[2][(size_t)G4 * HH];       // packed Whh hi/lo  [n=j*4+band][k]
__device__ __nv_bfloat16 g_wipk[2][(size_t)G4 * XP];      // packed Wih hi/lo
__device__ __nv_bfloat16 g_xpk[2][(size_t)TT * BB * XP];  // packed x hi/lo, row = t*BB+b
__device__ float g_bsum[G4];                              // permuted bias
__device__ float g_xg[(size_t)TT * BB * G4];              // xg + bias, fp32

// ---------------- helpers ----------------
__device__ __forceinline__ uint32_t s2u(const void* p) {
    uint32_t a;
    asm("{ .reg .u64 t; cvta.to.shared.u64 t, %1; cvt.u32.u64 %0, t; }" : "=r"(a) : "l"(p));
    return a;
}
#define CP16(d, s) asm volatile("cp.async.cg.shared.global [%0], [%1], 16;" ::"r"(d), "l"(s) : "memory")
#define CPCOMMIT() asm volatile("cp.async.commit_group;" ::: "memory")
#define LDSM4(r, a)                                                                      \
    asm volatile("ldmatrix.sync.aligned.m8n8.x4.shared.b16 {%0,%1,%2,%3}, [%4];"         \
                 : "=r"((r)[0]), "=r"((r)[1]), "=r"((r)[2]), "=r"((r)[3]) : "r"(a))
#define MMA(acc, a, b0, b1)                                                              \
    asm volatile("mma.sync.aligned.m16n8k16.row.col.f32.bf16.bf16.f32 "                  \
                 "{%0,%1,%2,%3}, {%4,%5,%6,%7}, {%8,%9}, {%0,%1,%2,%3};"                 \
                 : "+f"((acc)[0]), "+f"((acc)[1]), "+f"((acc)[2]), "+f"((acc)[3])        \
                 : "r"((a)[0]), "r"((a)[1]), "r"((a)[2]), "r"((a)[3]), "r"(b0), "r"(b1))

// fused 3-term compute over one K=64 chunk. Warp tile (TM*16) x 32.
// smem tiles: row-major [rows][64 bf16], 128B/row, swizzle off ^ ((row&7)<<4).
template <int TM>
__device__ __forceinline__ void fused3_chunk(
    uint32_t sAh, uint32_t sAl, uint32_t sBh, uint32_t sBl,
    int mbase, int nbase, int lane, float acc[TM][4][4])
{
#pragma unroll
    for (int kk = 0; kk < 4; kk++) {
        uint32_t bh[2][4], bl[2][4];
#pragma unroll
        for (int tn = 0; tn < 2; tn++) {
            const uint32_t g = (uint32_t)(lane >> 3);
            const uint32_t row = (uint32_t)(nbase + tn * 16) + ((g >> 1) << 3) + (uint32_t)(lane & 7);
            const uint32_t kb = (uint32_t)(kk * 32) + ((g & 1u) << 4);
            const uint32_t off = row * 128u + (kb ^ ((row & 7u) << 4));
            LDSM4(bh[tn], sBh + off);
            LDSM4(bl[tn], sBl + off);
        }
#pragma unroll
        for (int tm = 0; tm < TM; tm++) {
            uint32_t ah[4], al[4];
            const uint32_t row = (uint32_t)(mbase + tm * 16 + (lane & 15));
            const uint32_t kb = (uint32_t)(kk * 32) + ((uint32_t)(lane >> 4) << 4);
            const uint32_t off = row * 128u + (kb ^ ((row & 7u) << 4));
            LDSM4(ah, sAh + off);
            LDSM4(al, sAl + off);
#pragma unroll
            for (int tn = 0; tn < 4; tn++)
                MMA(acc[tm][tn], ah, bh[tn >> 1][(tn & 1) * 2], bh[tn >> 1][(tn & 1) * 2 + 1]);
#pragma unroll
            for (int tn = 0; tn < 4; tn++)
                MMA(acc[tm][tn], al, bh[tn >> 1][(tn & 1) * 2], bh[tn >> 1][(tn & 1) * 2 + 1]);
#pragma unroll
            for (int tn = 0; tn < 4; tn++)
                MMA(acc[tm][tn], ah, bl[tn >> 1][(tn & 1) * 2], bl[tn >> 1][(tn & 1) * 2 + 1]);
        }
    }
}

template <int TM>
__device__ __forceinline__ void store_acc(float* sacc, int pitch, float acc[TM][4][4],
                                          int mbase, int nbase, int lane) {
#pragma unroll
    for (int tm = 0; tm < TM; tm++)
#pragma unroll
        for (int tn = 0; tn < 4; tn++) {
            const int r = mbase + tm * 16 + (lane >> 2);
            const int cc = nbase + tn * 8 + (lane & 3) * 2;
            *(float2*)&sacc[r * pitch + cc] = make_float2(acc[tm][tn][0], acc[tm][tn][1]);
            *(float2*)&sacc[(r + 8) * pitch + cc] = make_float2(acc[tm][tn][2], acc[tm][tn][3]);
        }
}

// ---------------- prep kernels ----------------
__global__ void init_kernel() {
    int i = blockIdx.x * blockDim.x + threadIdx.x;
    if (i < BB * HH) {
        g_h[0][0][i] = __float2bfloat16(0.f);
        g_h[0][1][i] = __float2bfloat16(0.f);
        g_c[i] = 0.f;
    }
}

__global__ void prep_w(const float* __restrict__ Whh) {
    size_t i = (size_t)blockIdx.x * 256 + threadIdx.x;
    if (i >= (size_t)G4 * HH) return;
    int n = (int)(i / HH), k = (int)(i % HH);
    int j = n >> 2, band = n & 3, gc = band * HH + j;
    float w = Whh[(size_t)gc * HH + k];
    __nv_bfloat16 hi = __float2bfloat16(w);
    g_wpk[0][i] = hi;
    g_wpk[1][i] = __float2bfloat16(w - __bfloat162float(hi));
}

__global__ void prep_wi(const float* __restrict__ Wih, const float* __restrict__ bih,
                        const float* __restrict__ bhh) {
    size_t i = (size_t)blockIdx.x * 256 + threadIdx.x;
    if (i >= (size_t)G4 * XP) return;
    int n = (int)(i / XP), k = (int)(i % XP);
    int j = n >> 2, band = n & 3, gc = band * HH + j;
    float w = (k < DD) ? Wih[(size_t)gc * DD + k] : 0.f;
    __nv_bfloat16 hi = __float2bfloat16(w);
    g_wipk[0][i] = hi;
    g_wipk[1][i] = __float2bfloat16(w - __bfloat162float(hi));
    if (k == 0) g_bsum[n] = bih[gc] + bhh[gc];
}

__global__ void prep_x(const float* __restrict__ xt, const float* __restrict__ xa,
                       const float* __restrict__ xv) {
    size_t i = (size_t)blockIdx.x * 256 + threadIdx.x;
    if (i >= (size_t)TT * BB * XP) return;
    int d = (int)(i % XP);
    size_t tb = i / XP;
    int b = (int)(tb % BB), t = (int)(tb / BB);
    float v = 0.f;
    if (d < D_TXT)              v = xt[((size_t)b * TT + t) * D_TXT + d];
    else if (d < D_TXT + D_AUD) v = xa[((size_t)b * TT + t) * D_AUD + (d - D_TXT)];
    else if (d < DD)            v = xv[((size_t)b * TT + t) * D_VIS + (d - D_TXT - D_AUD)];
    __nv_bfloat16 hi = __float2bfloat16(v);
    g_xpk[0][i] = hi;
    g_xpk[1][i] = __float2bfloat16(v - __bfloat162float(hi));
}

// ---------------- xg GEMM: xg = x @ Wih^T + bias ----------------
// 128x128 tiles, grid (32, 512). 7 chunks of K=64, 3 stages x 64KB.
// stage layout: Ah 0 | Al 16K | Bh 32K | Bl 48K
#define XG_PITCH 132
#define XG_SSTRIDE 65536u
__global__ __launch_bounds__(256, 1) void xg_kernel() {
    extern __shared__ char dsm[];
    const int tid = threadIdx.x;
    const int lane = tid & 31, wid = tid >> 5;
    const int wy = wid >> 2, wx = wid & 3;
    const int r0 = blockIdx.y * 128, n0 = blockIdx.x * 128;
    const uint32_t sb = s2u(dsm);

    // loader: A: thread t -> hi/lo buf t>>7, row t&127 (8 CP16)
    //         B: thread t -> hi/lo buf t>>7, row t&127 (8 CP16)
    const int abuf = tid >> 7, arow = tid & 127;
    const uint32_t aswz = ((uint32_t)(arow & 7)) << 4;

    auto load_chunk = [&](int ck) {
        const uint32_t stage = sb + (uint32_t)(ck % 3) * XG_SSTRIDE;
        const char* asrc = (const char*)(g_xpk[abuf] + (size_t)(r0 + arow) * XP + ck * 64);
        const uint32_t ad = stage + (uint32_t)abuf * 16384u + (uint32_t)arow * 128u;
#pragma unroll
        for (int s = 0; s < 8; s++) CP16(ad + ((uint32_t)(s * 16) ^ aswz), asrc + s * 16);
        const char* bsrc = (const char*)(g_wipk[abuf] + (size_t)(n0 + arow) * XP + ck * 64);
        const uint32_t bd = stage + 32768u + (uint32_t)abuf * 16384u + (uint32_t)arow * 128u;
#pragma unroll
        for (int s = 0; s < 8; s++) CP16(bd + ((uint32_t)(s * 16) ^ aswz), bsrc + s * 16);
        CPCOMMIT();
    };

    float acc[4][4][4];
#pragma unroll
    for (int i = 0; i < 4; i++)
#pragma unroll
        for (int j = 0; j < 4; j++)
#pragma unroll
            for (int k = 0; k < 4; k++) acc[i][j][k] = 0.f;

    load_chunk(0);
    load_chunk(1);
#pragma unroll 1
    for (int ck = 0; ck < 7; ck++) {
        if (ck + 1 < 7) asm volatile("cp.async.wait_group 1;" ::: "memory");
        else            asm volatile("cp.async.wait_group 0;" ::: "memory");
        __syncthreads();
        if (ck + 2 < 7) load_chunk(ck + 2);
        const uint32_t stage = sb + (uint32_t)(ck % 3) * XG_SSTRIDE;
        fused3_chunk<4>(stage, stage + 16384u, stage + 32768u, stage + 49152u,
                        wy * 64, wx * 32, lane, acc);
    }
    __syncthreads();

    float* sacc = (float*)dsm;
    store_acc<4>(sacc, XG_PITCH, acc, wy * 64, wx * 32, lane);
    __syncthreads();
    for (int e = tid; e < 128 * 32; e += 256) {
        const int m = e >> 5, q = e & 31;
        float4 g = *(float4*)&sacc[m * XG_PITCH + q * 4];
        const float4 bs = *(const float4*)&g_bsum[n0 + q * 4];
        g.x += bs.x; g.y += bs.y; g.z += bs.z; g.w += bs.w;
        *(float4*)&g_xg[(size_t)(r0 + m) * G4 + n0 + q * 4] = g;
    }
}

// ---------------- LSTM step: gates = h @ Whh^T + xg; cell update ----------------
// 128(m) x 64(n) tiles, grid (64, 2) = 128 CTAs. 16 chunks, 3 stages x 48KB.
// stage layout: Ah 0 | Al 16K | Bh 32K | Bl 40K
#define ST_PITCH 68
#define ST_SSTRIDE 49152u
__global__ __launch_bounds__(256, 1) void step_kernel(int t) {
    extern __shared__ char dsm[];
    const int tid = threadIdx.x;
    const int lane = tid & 31, wid = tid >> 5;
    const int wy = wid >> 1, wx = wid & 1;     // warp grid 4(m) x 2(n), warp tile 32x32
    const int m0 = blockIdx.y * 128, n0 = blockIdx.x * 64;
    const int rb = t & 1, wb = rb ^ 1;
    const uint32_t sb = s2u(dsm);

    // loader: A: thread t -> buf t>>7, row t&127 (8 CP16)
    //         B: thread t -> rowidx t>>1 (buf rowidx>>6, row rowidx&63), half t&1 (4 CP16)
    const int abuf = tid >> 7, arow = tid & 127;
    const uint32_t aswz = ((uint32_t)(arow & 7)) << 4;
    const int bri = tid >> 1;
    const int bbuf = bri >> 6, brow = bri & 63, bhalf = tid & 1;
    const uint32_t bswz = ((uint32_t)(brow & 7)) << 4;

    auto load_chunk = [&](int ck) {
        const uint32_t stage = sb + (uint32_t)(ck % 3) * ST_SSTRIDE;
        const char* asrc = (const char*)(g_h[rb][abuf] + (size_t)(m0 + arow) * HH + ck * 64);
        const uint32_t ad = stage + (uint32_t)abuf * 16384u + (uint32_t)arow * 128u;
#pragma unroll
        for (int s = 0; s < 8; s++) CP16(ad + ((uint32_t)(s * 16) ^ aswz), asrc + s * 16);
        const char* bsrc = (const char*)(g_wpk[bbuf] + (size_t)(n0 + brow) * HH + ck * 64)
                           + bhalf * 64;
        const uint32_t bd = stage + 32768u + (uint32_t)bbuf * 8192u + (uint32_t)brow * 128u;
#pragma unroll
        for (int s = 0; s < 4; s++)
            CP16(bd + ((uint32_t)(bhalf * 64 + s * 16) ^ bswz), bsrc + s * 16);
        CPCOMMIT();
    };

    float acc[2][4][4];
#pragma unroll
    for (int i = 0; i < 2; i++)
#pragma unroll
        for (int j = 0; j < 4; j++)
#pragma unroll
            for (int k = 0; k < 4; k++) acc[i][j][k] = 0.f;

    load_chunk(0);
    load_chunk(1);
#pragma unroll 1
    for (int ck = 0; ck < 16; ck++) {
        if (ck + 1 < 16) asm volatile("cp.async.wait_group 1;" ::: "memory");
        else             asm volatile("cp.async.wait_group 0;" ::: "memory");
        __syncthreads();
        if (ck + 2 < 16) load_chunk(ck + 2);
        const uint32_t stage = sb + (uint32_t)(ck % 3) * ST_SSTRIDE;
        fused3_chunk<2>(stage, stage + 16384u, stage + 32768u, stage + 40960u,
                        wy * 32, wx * 32, lane, acc);
    }
    __syncthreads();

    float* sacc = (float*)dsm;
    store_acc<2>(sacc, ST_PITCH, acc, wy * 32, wx * 32, lane);
    __syncthreads();

    // cell update: packed n -> j = n>>2, bands i,f,g,o = n&3
    for (int e = tid; e < 128 * 16; e += 256) {
        const int m = e >> 4, q = e & 15;
        const float4 g = *(float4*)&sacc[m * ST_PITCH + q * 4];
        const size_t grow = (size_t)t * BB + (m0 + m);
        const float4 xgv = *(const float4*)&g_xg[grow * G4 + n0 + q * 4];
        const float gi = g.x + xgv.x;
        const float gf = g.y + xgv.y;
        const float gg = g.z + xgv.z;
        const float go = g.w + xgv.w;
        const float si = 1.f / (1.f + __expf(-gi));
        const float sf = 1.f / (1.f + __expf(-gf));
        const float tg = tanhf(gg);
        const float so = 1.f / (1.f + __expf(-go));
        const int j = (n0 >> 2) + q;
        const size_t idx = (size_t)(m0 + m) * HH + j;
        const float c = sf * g_c[idx] + si * tg;
        g_c[idx] = c;
        const float h = so * tanhf(c);
        const __nv_bfloat16 hh = __float2bfloat16(h);
        g_h[wb][0][idx] = hh;
        g_h[wb][1][idx] = __float2bfloat16(h - __bfloat162float(hh));
        if (t == TT - 1) g_hf[idx] = h;
    }
}

// ---------------- MLP head ----------------
__global__ __launch_bounds__(256) void mlp_kernel(
    const float* __restrict__ W1, const float* __restrict__ b1,
    const float* __restrict__ W2, const float* __restrict__ b2,
    float* __restrict__ out) {
    __shared__ float hrow[HH];
    __shared__ float red[256];
    const int b = blockIdx.x;
    const int tid = threadIdx.x;

    const float* __restrict__ h = &g_hf[(size_t)b * HH];
    for (int k = tid; k < HH; k += 256) hrow[k] = h[k];
    __syncthreads();

    float sum = 0.f;
    for (int cc = tid; cc < NCELL; cc += 256) {
        const float* __restrict__ w = &W1[(size_t)cc * HH];
        float acc = b1[cc];
        for (int k = 0; k < HH; k += 4) {
            const float4 wv = *(const float4*)&w[k];
            acc += hrow[k] * wv.x + hrow[k + 1] * wv.y + hrow[k + 2] * wv.z + hrow[k + 3] * wv.w;
        }
        sum += fmaxf(acc, 0.f) * W2[cc];
    }
    red[tid] = sum;
    __syncthreads();
    for (int s = 128; s > 0; s >>= 1) {
        if (tid < s) red[tid] += red[tid + s];
        __syncthreads();
    }
    if (tid == 0) out[b] = red[0] + b2[0];
}

// ---------------- launch ----------------
extern "C" void kernel_launch(void* const* d_in, const int* in_sizes, int n_in,
                              void* d_out, int out_size) {
    const float* xt  = (const float*)d_in[0];
    const float* xa  = (const float*)d_in[1];
    const float* xv  = (const float*)d_in[2];
    const float* Wih = (const float*)d_in[3];
    const float* Whh = (const float*)d_in[4];
    const float* bih = (const float*)d_in[5];
    const float* bhh = (const float*)d_in[6];
    const float* W1  = (const float*)d_in[7];
    const float* b1  = (const float*)d_in[8];
    const float* W2  = (const float*)d_in[9];
    const float* b2  = (const float*)d_in[10];
    float* out = (float*)d_out;

    const int DSM_XG = 3 * 65536;   // 192KB: 3 stages x (Ah|Al|Bh|Bl)
    const int DSM_ST = 3 * 49152;   // 144KB
    cudaFuncSetAttribute(xg_kernel, cudaFuncAttributeMaxDynamicSharedMemorySize, DSM_XG);
    cudaFuncSetAttribute(step_kernel, cudaFuncAttributeMaxDynamicSharedMemorySize, DSM_ST);

    init_kernel<<<(BB * HH + 255) / 256, 256>>>();
    prep_w<<<(int)(((size_t)G4 * HH + 255) / 256), 256>>>(Whh);
    prep_wi<<<(int)(((size_t)G4 * XP + 255) / 256), 256>>>(Wih, bih, bhh);
    prep_x<<<(int)(((size_t)TT * BB * XP + 255) / 256), 256>>>(xt, xa, xv);
    xg_kernel<<<dim3(32, 512), 256, DSM_XG>>>();
    for (int t = 0; t < TT; t++)
        step_kernel<<<dim3(64, 2), 256, DSM_ST>>>(t);
    mlp_kernel<<<BB, 256>>>(W1, b1, W2, b2, out);
}

// round 7
// speedup vs baseline: 4.1335x; 1.7686x over previous
#include <cuda_runtime.h>
#include <cuda_bf16.h>
#include <cstdint>

// EFLSTM via warp-level bf16x3 mma.sync + 1D cp.async.bulk (UBLKCP) tile staging.
// Packed gmem layouts are chunk-major and PRE-SWIZZLED (exact smem image), so each
// chunk tile is ONE contiguous bulk copy: 4 bulk ops/chunk instead of 3072 LDGSTS.
//   phase 1: xg[t,b,:] = x @ Wih^T + bias   (parallel GEMM, fp32, 1GB scratch)
//   phase 2: 256 sequential steps: gates = h @ Whh^T + xg; fused LSTM cell update
//   phase 3: MLP head
// Gate cols permuted n = j*4 + band so the cell update is CTA-local.
// bf16x3: Ah*Bh + Al*Bh + Ah*Bl accumulated fp32, all 3 terms per K-chunk.

#define BB 256
#define TT 256
#define D_TXT 300
#define D_AUD 74
#define D_VIS 35
#define DD 409
#define HH 1024
#define G4 4096
#define XP 448
#define NCELL 512

// ---------------- device scratch ----------------
// h packed: [buf][hi/lo][chunk 0..15][row 0..255][64 bf16], swizzled image
__device__ __nv_bfloat16 g_hp[2][2][16 * 256 * 64];
__device__ float g_c[BB * HH];
__device__ float g_hf[BB * HH];
// Whh packed: [hi/lo][chunk 0..15][n 0..4095][64], swizzled image
__device__ __nv_bfloat16 g_wpk[2][(size_t)16 * G4 * 64];
// Wih packed: [hi/lo][chunk 0..6][n 0..4095][64], swizzled image
__device__ __nv_bfloat16 g_wipk[2][(size_t)7 * G4 * 64];
// x packed: [hi/lo][t][chunk 0..6][b 0..255][64], swizzled image
__device__ __nv_bfloat16 g_xpk[2][(size_t)TT * 7 * BB * 64];
__device__ float g_bsum[G4];                 // permuted bias
__device__ float g_xg[(size_t)TT * BB * G4]; // xg + bias, fp32

// ---------------- helpers ----------------
__device__ __forceinline__ uint32_t s2u(const void* p) {
    uint32_t a;
    asm("{ .reg .u64 t; cvta.to.shared.u64 t, %1; cvt.u32.u64 %0, t; }" : "=r"(a) : "l"(p));
    return a;
}
#define MBINIT(a, c) asm volatile("mbarrier.init.shared.b64 [%0], %1;" ::"r"(a), "r"(c) : "memory")
#define MBWAIT(a, ph) do {                                                                  \
    uint32_t _d;                                                                            \
    asm volatile("{\n .reg .pred p;\n mbarrier.try_wait.parity.acquire.cta.shared::cta.b64 p,[%1],%2;\n selp.b32 %0,1,0,p;\n}" \
                 : "=r"(_d) : "r"(a), "r"(ph) : "memory");                                  \
    while (!_d) {                                                                           \
        asm volatile("{\n .reg .pred p;\n mbarrier.try_wait.parity.acquire.cta.shared::cta.b64 p,[%1],%2,0x989680;\n selp.b32 %0,1,0,p;\n}" \
                     : "=r"(_d) : "r"(a), "r"(ph) : "memory");                              \
    }                                                                                       \
} while (0)
#define MBEXPECT(bar, bytes) \
    asm volatile("mbarrier.arrive.expect_tx.shared.b64 _, [%0], %1;" ::"r"(bar), "r"(bytes) : "memory")
#define BULK(dst, src, bytes, bar)                                                          \
    asm volatile("cp.async.bulk.shared::cluster.global.mbarrier::complete_tx::bytes "       \
                 "[%0], [%1], %2, [%3];"                                                    \
                 ::"r"(dst), "l"((const void*)(src)), "r"(bytes), "r"(bar) : "memory")
#define LDSM4(r, a)                                                                         \
    asm volatile("ldmatrix.sync.aligned.m8n8.x4.shared.b16 {%0,%1,%2,%3}, [%4];"            \
                 : "=r"((r)[0]), "=r"((r)[1]), "=r"((r)[2]), "=r"((r)[3]) : "r"(a))
#define MMA(acc, a, b0, b1)                                                                 \
    asm volatile("mma.sync.aligned.m16n8k16.row.col.f32.bf16.bf16.f32 "                     \
                 "{%0,%1,%2,%3}, {%4,%5,%6,%7}, {%8,%9}, {%0,%1,%2,%3};"                    \
                 : "+f"((acc)[0]), "+f"((acc)[1]), "+f"((acc)[2]), "+f"((acc)[3])           \
                 : "r"((a)[0]), "r"((a)[1]), "r"((a)[2]), "r"((a)[3]), "r"(b0), "r"(b1))

// fused 3-term compute over one K=64 chunk. Warp tile (TM*16) x 32.
// smem tiles: row-major [rows][64 bf16], 128B/row, swizzle off ^ ((row&7)<<4).
template <int TM>
__device__ __forceinline__ void fused3_chunk(
    uint32_t sAh, uint32_t sAl, uint32_t sBh, uint32_t sBl,
    int mbase, int nbase, int lane, float acc[TM][4][4])
{
#pragma unroll
    for (int kk = 0; kk < 4; kk++) {
        uint32_t bh[2][4], bl[2][4];
#pragma unroll
        for (int tn = 0; tn < 2; tn++) {
            const uint32_t g = (uint32_t)(lane >> 3);
            const uint32_t row = (uint32_t)(nbase + tn * 16) + ((g >> 1) << 3) + (uint32_t)(lane & 7);
            const uint32_t kb = (uint32_t)(kk * 32) + ((g & 1u) << 4);
            const uint32_t off = row * 128u + (kb ^ ((row & 7u) << 4));
            LDSM4(bh[tn], sBh + off);
            LDSM4(bl[tn], sBl + off);
        }
#pragma unroll
        for (int tm = 0; tm < TM; tm++) {
            uint32_t ah[4], al[4];
            const uint32_t row = (uint32_t)(mbase + tm * 16 + (lane & 15));
            const uint32_t kb = (uint32_t)(kk * 32) + ((uint32_t)(lane >> 4) << 4);
            const uint32_t off = row * 128u + (kb ^ ((row & 7u) << 4));
            LDSM4(ah, sAh + off);
            LDSM4(al, sAl + off);
#pragma unroll
            for (int tn = 0; tn < 4; tn++)
                MMA(acc[tm][tn], ah, bh[tn >> 1][(tn & 1) * 2], bh[tn >> 1][(tn & 1) * 2 + 1]);
#pragma unroll
            for (int tn = 0; tn < 4; tn++)
                MMA(acc[tm][tn], al, bh[tn >> 1][(tn & 1) * 2], bh[tn >> 1][(tn & 1) * 2 + 1]);
#pragma unroll
            for (int tn = 0; tn < 4; tn++)
                MMA(acc[tm][tn], ah, bl[tn >> 1][(tn & 1) * 2], bl[tn >> 1][(tn & 1) * 2 + 1]);
        }
    }
}

template <int TM>
__device__ __forceinline__ void store_acc(float* sacc, int pitch, float acc[TM][4][4],
                                          int mbase, int nbase, int lane) {
#pragma unroll
    for (int tm = 0; tm < TM; tm++)
#pragma unroll
        for (int tn = 0; tn < 4; tn++) {
            const int r = mbase + tm * 16 + (lane >> 2);
            const int cc = nbase + tn * 8 + (lane & 3) * 2;
            *(float2*)&sacc[r * pitch + cc] = make_float2(acc[tm][tn][0], acc[tm][tn][1]);
            *(float2*)&sacc[(r + 8) * pitch + cc] = make_float2(acc[tm][tn][2], acc[tm][tn][3]);
        }
}

// ---------------- prep kernels (write pre-swizzled chunk-major images) ----------------
__global__ void init_kernel() {
    int i = blockIdx.x * blockDim.x + threadIdx.x;
    if (i < BB * HH) {
        g_hp[0][0][i] = __float2bfloat16(0.f);
        g_hp[0][1][i] = __float2bfloat16(0.f);
        g_c[i] = 0.f;
    }
}

__global__ void prep_w(const float* __restrict__ Whh) {
    size_t i = (size_t)blockIdx.x * 256 + threadIdx.x;
    if (i >= (size_t)G4 * HH) return;
    int n = (int)(i / HH), k = (int)(i % HH);
    int j = n >> 2, band = n & 3, gc = band * HH + j;
    float w = Whh[(size_t)gc * HH + k];
    __nv_bfloat16 hi = __float2bfloat16(w);
    int ck = k >> 6, col = k & 63;
    int unit = (col >> 3) ^ (n & 7);
    size_t oi = ((size_t)ck * G4 + n) * 64 + unit * 8 + (col & 7);
    g_wpk[0][oi] = hi;
    g_wpk[1][oi] = __float2bfloat16(w - __bfloat162float(hi));
}

__global__ void prep_wi(const float* __restrict__ Wih, const float* __restrict__ bih,
                        const float* __restrict__ bhh) {
    size_t i = (size_t)blockIdx.x * 256 + threadIdx.x;
    if (i >= (size_t)G4 * XP) return;
    int n = (int)(i / XP), k = (int)(i % XP);
    int j = n >> 2, band = n & 3, gc = band * HH + j;
    float w = (k < DD) ? Wih[(size_t)gc * DD + k] : 0.f;
    __nv_bfloat16 hi = __float2bfloat16(w);
    int ck = k >> 6, col = k & 63;
    int unit = (col >> 3) ^ (n & 7);
    size_t oi = ((size_t)ck * G4 + n) * 64 + unit * 8 + (col & 7);
    g_wipk[0][oi] = hi;
    g_wipk[1][oi] = __float2bfloat16(w - __bfloat162float(hi));
    if (k == 0) g_bsum[n] = bih[gc] + bhh[gc];
}

__global__ void prep_x(const float* __restrict__ xt, const float* __restrict__ xa,
                       const float* __restrict__ xv) {
    size_t i = (size_t)blockIdx.x * 256 + threadIdx.x;
    if (i >= (size_t)TT * BB * XP) return;
    int d = (int)(i % XP);
    size_t tb = i / XP;
    int b = (int)(tb % BB), t = (int)(tb / BB);
    float v = 0.f;
    if (d < D_TXT)              v = xt[((size_t)b * TT + t) * D_TXT + d];
    else if (d < D_TXT + D_AUD) v = xa[((size_t)b * TT + t) * D_AUD + (d - D_TXT)];
    else if (d < DD)            v = xv[((size_t)b * TT + t) * D_VIS + (d - D_TXT - D_AUD)];
    __nv_bfloat16 hi = __float2bfloat16(v);
    int ck = d >> 6, col = d & 63;
    int unit = (col >> 3) ^ (b & 7);
    size_t oi = (((size_t)t * 7 + ck) * BB + b) * 64 + unit * 8 + (col & 7);
    g_xpk[0][oi] = hi;
    g_xpk[1][oi] = __float2bfloat16(v - __bfloat162float(hi));
}

// ---------------- xg GEMM: xg = x @ Wih^T + bias ----------------
// 128x128 tiles, grid (32, 512). 7 chunks, 3 stages x 64KB (Ah|Al|Bh|Bl).
#define XG_PITCH 132
#define XG_STAGE 65536u
__global__ __launch_bounds__(256, 1) void xg_kernel() {
    extern __shared__ __align__(128) char dsm[];
    __shared__ __align__(8) uint64_t s_mbar[3];
    const int tid = threadIdx.x;
    const int lane = tid & 31, wid = tid >> 5;
    const int wy = wid >> 2, wx = wid & 3;
    const int r0 = blockIdx.y * 128, n0 = blockIdx.x * 128;
    const int t = blockIdx.y >> 1, b0 = (blockIdx.y & 1) * 128;
    const uint32_t sb = s2u(dsm);
    const uint32_t mb = s2u(s_mbar);

    if (tid == 0) { MBINIT(mb, 1); MBINIT(mb + 8, 1); MBINIT(mb + 16, 1); }
    __syncthreads();

    auto issue = [&](int ck) {
        const uint32_t stage = sb + (uint32_t)(ck % 3) * XG_STAGE;
        const uint32_t bar = mb + (uint32_t)(ck % 3) * 8;
        MBEXPECT(bar, 65536u);
        BULK(stage,           &g_xpk[0][(((size_t)t * 7 + ck) * BB + b0) * 64], 16384u, bar);
        BULK(stage + 16384u,  &g_xpk[1][(((size_t)t * 7 + ck) * BB + b0) * 64], 16384u, bar);
        BULK(stage + 32768u,  &g_wipk[0][((size_t)ck * G4 + n0) * 64],          16384u, bar);
        BULK(stage + 49152u,  &g_wipk[1][((size_t)ck * G4 + n0) * 64],          16384u, bar);
    };
    if (tid == 0) { issue(0); issue(1); issue(2); }

    float acc[4][4][4];
#pragma unroll
    for (int i = 0; i < 4; i++)
#pragma unroll
        for (int j = 0; j < 4; j++)
#pragma unroll
            for (int k = 0; k < 4; k++) acc[i][j][k] = 0.f;

#pragma unroll 1
    for (int ck = 0; ck < 7; ck++) {
        MBWAIT(mb + (ck % 3) * 8, (ck / 3) & 1);
        const uint32_t stage = sb + (uint32_t)(ck % 3) * XG_STAGE;
        fused3_chunk<4>(stage, stage + 16384u, stage + 32768u, stage + 49152u,
                        wy * 64, wx * 32, lane, acc);
        __syncthreads();
        if (ck + 3 < 7 && tid == 0) issue(ck + 3);
    }

    float* sacc = (float*)dsm;
    store_acc<4>(sacc, XG_PITCH, acc, wy * 64, wx * 32, lane);
    __syncthreads();
    for (int e = tid; e < 128 * 32; e += 256) {
        const int m = e >> 5, q = e & 31;
        float4 g = *(float4*)&sacc[m * XG_PITCH + q * 4];
        const float4 bs = *(const float4*)&g_bsum[n0 + q * 4];
        g.x += bs.x; g.y += bs.y; g.z += bs.z; g.w += bs.w;
        *(float4*)&g_xg[(size_t)(r0 + m) * G4 + n0 + q * 4] = g;
    }
}

// ---------------- LSTM step: gates = h @ Whh^T + xg; cell update ----------------
// 128(m) x 64(n) tiles, grid (64, 2) = 128 CTAs. 16 chunks, 3 stages x 48KB.
#define ST_PITCH 68
#define ST_STAGE 49152u
__global__ __launch_bounds__(256, 1) void step_kernel(int t) {
    extern __shared__ __align__(128) char dsm[];
    __shared__ __align__(8) uint64_t s_mbar[3];
    const int tid = threadIdx.x;
    const int lane = tid & 31, wid = tid >> 5;
    const int wy = wid >> 1, wx = wid & 1;   // warp grid 4(m) x 2(n), warp tile 32x32
    const int m0 = blockIdx.y * 128, n0 = blockIdx.x * 64;
    const int rb = t & 1, wb = rb ^ 1;
    const uint32_t sb = s2u(dsm);
    const uint32_t mb = s2u(s_mbar);

    if (tid == 0) { MBINIT(mb, 1); MBINIT(mb + 8, 1); MBINIT(mb + 16, 1); }
    __syncthreads();

    auto issue = [&](int ck) {
        const uint32_t stage = sb + (uint32_t)(ck % 3) * ST_STAGE;
        const uint32_t bar = mb + (uint32_t)(ck % 3) * 8;
        MBEXPECT(bar, 49152u);
        BULK(stage,           &g_hp[rb][0][((size_t)ck * 256 + m0) * 64], 16384u, bar);
        BULK(stage + 16384u,  &g_hp[rb][1][((size_t)ck * 256 + m0) * 64], 16384u, bar);
        BULK(stage + 32768u,  &g_wpk[0][((size_t)ck * G4 + n0) * 64],      8192u, bar);
        BULK(stage + 40960u,  &g_wpk[1][((size_t)ck * G4 + n0) * 64],      8192u, bar);
    };
    if (tid == 0) { issue(0); issue(1); issue(2); }

    float acc[2][4][4];
#pragma unroll
    for (int i = 0; i < 2; i++)
#pragma unroll
        for (int j = 0; j < 4; j++)
#pragma unroll
            for (int k = 0; k < 4; k++) acc[i][j][k] = 0.f;

#pragma unroll 1
    for (int ck = 0; ck < 16; ck++) {
        MBWAIT(mb + (ck % 3) * 8, (ck / 3) & 1);
        const uint32_t stage = sb + (uint32_t)(ck % 3) * ST_STAGE;
        fused3_chunk<2>(stage, stage + 16384u, stage + 32768u, stage + 40960u,
                        wy * 32, wx * 32, lane, acc);
        __syncthreads();
        if (ck + 3 < 16 && tid == 0) issue(ck + 3);
    }

    float* sacc = (float*)dsm;
    store_acc<2>(sacc, ST_PITCH, acc, wy * 32, wx * 32, lane);
    __syncthreads();

    // cell update: packed n -> j = n>>2, bands i,f,g,o = n&3
    for (int e = tid; e < 128 * 16; e += 256) {
        const int mloc = e >> 4, q = e & 15;
        const int gm = m0 + mloc;
        const float4 g = *(float4*)&sacc[mloc * ST_PITCH + q * 4];
        const float4 xgv = *(const float4*)&g_xg[((size_t)t * BB + gm) * G4 + n0 + q * 4];
        const float gi = g.x + xgv.x;
        const float gf = g.y + xgv.y;
        const float gg = g.z + xgv.z;
        const float go = g.w + xgv.w;
        const float si = 1.f / (1.f + __expf(-gi));
        const float sf = 1.f / (1.f + __expf(-gf));
        const float tg = tanhf(gg);
        const float so = 1.f / (1.f + __expf(-go));
        const int j = (n0 >> 2) + q;
        const size_t cidx = (size_t)gm * HH + j;
        const float c = sf * g_c[cidx] + si * tg;
        g_c[cidx] = c;
        const float h = so * tanhf(c);
        const __nv_bfloat16 hh = __float2bfloat16(h);
        // write packed swizzled h image
        const int ck = j >> 6, col = j & 63;
        const int unit = (col >> 3) ^ (gm & 7);
        const size_t hidx = ((size_t)ck * 256 + gm) * 64 + unit * 8 + (col & 7);
        g_hp[wb][0][hidx] = hh;
        g_hp[wb][1][hidx] = __float2bfloat16(h - __bfloat162float(hh));
        if (t == TT - 1) g_hf[cidx] = h;
    }
}

// ---------------- MLP head ----------------
__global__ __launch_bounds__(256) void mlp_kernel(
    const float* __restrict__ W1, const float* __restrict__ b1,
    const float* __restrict__ W2, const float* __restrict__ b2,
    float* __restrict__ out) {
    __shared__ float hrow[HH];
    __shared__ float red[256];
    const int b = blockIdx.x;
    const int tid = threadIdx.x;

    const float* __restrict__ h = &g_hf[(size_t)b * HH];
    for (int k = tid; k < HH; k += 256) hrow[k] = h[k];
    __syncthreads();

    float sum = 0.f;
    for (int cc = tid; cc < NCELL; cc += 256) {
        const float* __restrict__ w = &W1[(size_t)cc * HH];
        float acc = b1[cc];
        for (int k = 0; k < HH; k += 4) {
            const float4 wv = *(const float4*)&w[k];
            acc += hrow[k] * wv.x + hrow[k + 1] * wv.y + hrow[k + 2] * wv.z + hrow[k + 3] * wv.w;
        }
        sum += fmaxf(acc, 0.f) * W2[cc];
    }
    red[tid] = sum;
    __syncthreads();
    for (int s = 128; s > 0; s >>= 1) {
        if (tid < s) red[tid] += red[tid + s];
        __syncthreads();
    }
    if (tid == 0) out[b] = red[0] + b2[0];
}

// ---------------- launch ----------------
extern "C" void kernel_launch(void* const* d_in, const int* in_sizes, int n_in,
                              void* d_out, int out_size) {
    const float* xt  = (const float*)d_in[0];
    const float* xa  = (const float*)d_in[1];
    const float* xv  = (const float*)d_in[2];
    const float* Wih = (const float*)d_in[3];
    const float* Whh = (const float*)d_in[4];
    const float* bih = (const float*)d_in[5];
    const float* bhh = (const float*)d_in[6];
    const float* W1  = (const float*)d_in[7];
    const float* b1  = (const float*)d_in[8];
    const float* W2  = (const float*)d_in[9];
    const float* b2  = (const float*)d_in[10];
    float* out = (float*)d_out;

    const int DSM_XG = 3 * 65536;   // 192KB
    const int DSM_ST = 3 * 49152;   // 144KB
    cudaFuncSetAttribute(xg_kernel, cudaFuncAttributeMaxDynamicSharedMemorySize, DSM_XG);
    cudaFuncSetAttribute(step_kernel, cudaFuncAttributeMaxDynamicSharedMemorySize, DSM_ST);

    init_kernel<<<(BB * HH + 255) / 256, 256>>>();
    prep_w<<<(int)(((size_t)G4 * HH + 255) / 256), 256>>>(Whh);
    prep_wi<<<(int)(((size_t)G4 * XP + 255) / 256), 256>>>(Wih, bih, bhh);
    prep_x<<<(int)(((size_t)TT * BB * XP + 255) / 256), 256>>>(xt, xa, xv);
    xg_kernel<<<dim3(32, 512), 256, DSM_XG>>>();
    for (int t = 0; t < TT; t++)
        step_kernel<<<dim3(64, 2), 256, DSM_ST>>>(t);
    mlp_kernel<<<BB, 256>>>(W1, b1, W2, b2, out);
}